// round 11
// baseline (speedup 1.0000x reference)
#include <cuda_runtime.h>
#include <cuda_fp16.h>

#define NN  50000
#define EE  1200000
#define NIDD 92
#define HH  64
#define LL  5
#define GG  256
#define M1  129   // 2H + ED
#define NSCAN 196 // ceil(NN/256)

// ---------------- device scratch (no mallocs allowed) ----------------
__device__ float   g_h[NN * HH];        // node features (post-activation)
__device__ float   g_u[NN * HH];        // update pre-activation
__device__ float   g_aggy[NN * HH];     // sum of silu(BN(z1)) over incoming edges
__device__ float   g_pt[NN * HH];       // h @ W1[0:64] + b1 (dst part), fp32
__device__ __half2 g_pmh[NN * 32];      // h @ W1[64:128] (src part), packed (c, c+32)
__device__ int     g_degi[NN];          // in-degree
__device__ int     g_off[NN];           // CSR offsets
__device__ int     g_cur[NN];           // CSR scatter cursors
__device__ int     g_bsum[NSCAN];       // scan block sums (raw)
__device__ int2    g_cedge[EE];         // CSR: (src, ea bits) per slot
__device__ float   g_sumA[2 * LL * HH]; // BN stat slots (2 per layer)
__device__ float   g_sqA[2 * LL * HH];
__device__ float   g_wcA[LL * HH * HH]; // W2 @ updW_bot per layer
__device__ float   g_bcA[LL * HH];      // b2 @ updW_bot per layer
__device__ float   g_pool[GG * HH];
__device__ float   g_cnt[GG];

__device__ __forceinline__ float silu_f(float x) {
    return __fdividef(x, 1.0f + __expf(-x));
}

// fast silu: 1 MUFU (tanh.approx) instead of 2 (ex2 + rcp)
// silu(x) = x*sigmoid(x) = 0.5x*(1 + tanh(0.5x))
__device__ __forceinline__ float silu_fast(float x) {
    float h = 0.5f * x;
    float t;
    asm("tanh.approx.f32 %0, %1;" : "=f"(t) : "f"(h));
    return fmaf(h, t, h);
}

// inline BN coefficient finalize from a stat slot
__device__ __forceinline__ void bn_coef(int slot, int c, const float* __restrict__ gam,
                                        const float* __restrict__ bet, float denom,
                                        float& a, float& b) {
    float mean = g_sumA[slot * HH + c] / denom;
    float var  = g_sqA[slot * HH + c] / denom - mean * mean;
    float inv  = rsqrtf(var + 1e-5f);
    a = gam[c] * inv;
    b = bet[c] - mean * a;
}

// ---------------- init ----------------
__global__ void k_init() {
    int i = blockIdx.x * blockDim.x + threadIdx.x;
    int stride = gridDim.x * blockDim.x;
    for (int t = i; t < NN; t += stride) g_degi[t] = 0;
    for (int t = i; t < GG * HH; t += stride) g_pool[t] = 0.0f;
    for (int t = i; t < GG; t += stride) g_cnt[t] = 0.0f;
    for (int t = i; t < 2 * LL * HH; t += stride) { g_sumA[t] = 0.0f; g_sqA[t] = 0.0f; }
}

// ---------------- fold (all layers, hoisted): Wc = W2@Wu_bot ; bc = b2@Wu_bot -
__global__ void k_foldw(const float* __restrict__ W2all, const float* __restrict__ Wuall,
                        const float* __restrict__ b2all) {
    int l = blockIdx.y;
    const float* W2 = W2all + (size_t)l * HH * HH;
    const float* Wu = Wuall + (size_t)l * 2 * HH * HH;
    const float* b2 = b2all + l * HH;
    int i = blockIdx.x * blockDim.x + threadIdx.x;
    if (i < HH * HH) {
        int k = i >> 6, c = i & 63;
        float acc = 0.f;
        #pragma unroll 8
        for (int j = 0; j < HH; j++)
            acc += __ldg(&W2[k * HH + j]) * __ldg(&Wu[(HH + j) * HH + c]);
        g_wcA[l * HH * HH + i] = acc;
    } else if (i < HH * HH + HH) {
        int c = i - HH * HH;
        float acc = 0.f;
        #pragma unroll 8
        for (int j = 0; j < HH; j++)
            acc += __ldg(&b2[j]) * __ldg(&Wu[(HH + j) * HH + c]);
        g_bcA[l * HH + c] = acc;
    }
}

// ---------------- node embedding: h = x @ node_W + node_b ----------------
__global__ __launch_bounds__(256) void k_embed(const float* __restrict__ x,
                                               const float* __restrict__ W,
                                               const float* __restrict__ b) {
    __shared__ float sW[NIDD * HH];     // 23.5KB
    __shared__ float sx[8][NIDD];
    int tid = threadIdx.x;
    for (int i = tid; i < NIDD * HH; i += 256) sW[i] = W[i];
    __syncthreads();

    int warp = tid >> 5, lane = tid & 31;
    int gw = blockIdx.x * 8 + warp;
    int ws = gridDim.x * 8;
    float* xs = sx[warp];
    float b0 = b[lane], b1v = b[lane + 32];
    for (int n = gw; n < NN; n += ws) {
        xs[lane] = x[n * NIDD + lane];
        xs[32 + lane] = x[n * NIDD + 32 + lane];
        if (lane < NIDD - 64) xs[64 + lane] = x[n * NIDD + 64 + lane];
        __syncwarp();
        float a0 = b0, a1 = b1v;
        const float* wp = sW + lane;
        #pragma unroll 4
        for (int k = 0; k < NIDD; k++) {
            float xv = xs[k];
            a0 += xv * wp[0];
            a1 += xv * wp[32];
            wp += HH;
        }
        g_h[n * HH + lane] = a0;
        g_h[n * HH + lane + 32] = a1;
        __syncwarp();
    }
}

// ---------------- degree histogram ----------------
__global__ void k_deg(const int* __restrict__ dst) {
    int i = blockIdx.x * blockDim.x + threadIdx.x;
    int stride = gridDim.x * blockDim.x;
    for (int e = i; e < EE; e += stride) atomicAdd(&g_degi[dst[e]], 1);
}

// ---------------- scan phase 1: coalesced per-block sums ----------------
__global__ __launch_bounds__(256) void k_scan1() {
    int idx = blockIdx.x * 256 + threadIdx.x;
    int v = (idx < NN) ? g_degi[idx] : 0;
    #pragma unroll
    for (int o = 16; o; o >>= 1) v += __shfl_down_sync(0xffffffffu, v, o);
    __shared__ int ws[8];
    if ((threadIdx.x & 31) == 0) ws[threadIdx.x >> 5] = v;
    __syncthreads();
    if (threadIdx.x < 8) {
        int t = ws[threadIdx.x];
        #pragma unroll
        for (int o = 4; o; o >>= 1) t += __shfl_down_sync(0xffu, t, o);
        if (threadIdx.x == 0) g_bsum[blockIdx.x] = t;
    }
}

// ---------------- scan phase 2+3 merged: every block redundantly scans the
// 196 block sums in smem, then does its local exclusive scan + offset --------
__global__ __launch_bounds__(256) void k_scan3() {
    __shared__ int sb[256];
    __shared__ int s[256];
    int t = threadIdx.x;
    int bv = (t < NSCAN) ? g_bsum[t] : 0;
    sb[t] = bv;
    __syncthreads();
    #pragma unroll
    for (int o = 1; o < 256; o <<= 1) {
        int u = (t >= o) ? sb[t - o] : 0;
        __syncthreads();
        sb[t] += u;
        __syncthreads();
    }
    int blockOff = (blockIdx.x == 0) ? 0 : sb[blockIdx.x - 1];

    int idx = blockIdx.x * 256 + t;
    int v = (idx < NN) ? g_degi[idx] : 0;
    s[t] = v;
    __syncthreads();
    #pragma unroll
    for (int o = 1; o < 256; o <<= 1) {
        int u = (t >= o) ? s[t - o] : 0;
        __syncthreads();
        s[t] += u;
        __syncthreads();
    }
    int excl = s[t] - v + blockOff;
    if (idx < NN) { g_off[idx] = excl; g_cur[idx] = excl; }
}

// ---------------- CSR scatter: place (src, ea) by dst ----------------
__global__ void k_scatter(const int* __restrict__ src, const int* __restrict__ dst,
                          const float* __restrict__ ea) {
    int i = blockIdx.x * blockDim.x + threadIdx.x;
    int stride = gridDim.x * blockDim.x;
    for (int e = i; e < EE; e += stride) {
        int d = dst[e];
        int p = atomicAdd(&g_cur[d], 1);
        g_cedge[p] = make_int2(src[e], __float_as_int(ea[e]));
    }
}

// ---------------- per-node precompute: pt = h@W1_top + b1 ; pmh = h@W1_mid ---
// If prev_slot >= 0: h is first recomputed as silu(BN(u)) using that stat slot
// (fused update pass2 of the previous layer) and written back to g_h.
__global__ __launch_bounds__(256) void k_pre(const float* __restrict__ W1,
                                             const float* __restrict__ b1,
                                             const float* __restrict__ gamP,
                                             const float* __restrict__ betP,
                                             int prev_slot) {
    __shared__ float4 sW[16 * 128];              // 32KB
    __shared__ alignas(16) float sh[8][4][64];   // 8KB
    int tid = threadIdx.x;
    for (int idx = tid; idx < 16 * 128; idx += 256) {
        int c2 = idx & 127, k4 = idx >> 7;
        int col = c2 & 63;
        int row = (c2 < 64 ? 4 * k4 : 64 + 4 * k4);
        sW[idx] = make_float4(W1[row * HH + col], W1[(row + 1) * HH + col],
                              W1[(row + 2) * HH + col], W1[(row + 3) * HH + col]);
    }
    __syncthreads();

    int warp = tid >> 5, lane = tid & 31;
    float bt0 = b1[lane], bt1 = b1[lane + 32];
    float ga0 = 0.f, ga1 = 0.f, gb0 = 0.f, gb1 = 0.f;
    if (prev_slot >= 0) {
        bn_coef(prev_slot, lane,      gamP, betP, (float)NN, ga0, gb0);
        bn_coef(prev_slot, lane + 32, gamP, betP, (float)NN, ga1, gb1);
    }
    float (*hs)[64] = sh[warp];
    int tile = blockIdx.x * 8 + warp, ts = gridDim.x * 8;
    const int NT = NN / 4;
    for (int t = tile; t < NT; t += ts) {
        int n0 = t * 4;
        #pragma unroll
        for (int e = 0; e < 4; e++) {
            int n = n0 + e;
            float h0, h1;
            if (prev_slot >= 0) {
                h0 = silu_f(g_u[n * HH + lane]      * ga0 + gb0);
                h1 = silu_f(g_u[n * HH + lane + 32] * ga1 + gb1);
                g_h[n * HH + lane]      = h0;
                g_h[n * HH + lane + 32] = h1;
            } else {
                h0 = g_h[n * HH + lane];
                h1 = g_h[n * HH + lane + 32];
            }
            hs[e][lane]      = h0;
            hs[e][lane + 32] = h1;
        }
        __syncwarp();
        float a0[4], a1[4], a2[4], a3[4];
        #pragma unroll
        for (int e = 0; e < 4; e++) { a0[e] = 0.f; a1[e] = 0.f; a2[e] = 0.f; a3[e] = 0.f; }
        #pragma unroll
        for (int k4 = 0; k4 < 16; k4++) {
            float4 wA = sW[k4 * 128 + lane];
            float4 wB = sW[k4 * 128 + 32 + lane];
            float4 wC = sW[k4 * 128 + 64 + lane];
            float4 wD = sW[k4 * 128 + 96 + lane];
            #pragma unroll
            for (int e = 0; e < 4; e++) {
                float4 hv = *(const float4*)&hs[e][k4 * 4];
                a0[e] += hv.x * wA.x; a0[e] += hv.y * wA.y; a0[e] += hv.z * wA.z; a0[e] += hv.w * wA.w;
                a1[e] += hv.x * wB.x; a1[e] += hv.y * wB.y; a1[e] += hv.z * wB.z; a1[e] += hv.w * wB.w;
                a2[e] += hv.x * wC.x; a2[e] += hv.y * wC.y; a2[e] += hv.z * wC.z; a2[e] += hv.w * wC.w;
                a3[e] += hv.x * wD.x; a3[e] += hv.y * wD.y; a3[e] += hv.z * wD.z; a3[e] += hv.w * wD.w;
            }
        }
        #pragma unroll
        for (int e = 0; e < 4; e++) {
            int n = n0 + e;
            g_pt[n * HH + lane]      = a0[e] + bt0;
            g_pt[n * HH + lane + 32] = a1[e] + bt1;
            g_pmh[n * 32 + lane]     = __floats2half2_rn(a2[e], a3[e]);
        }
        __syncwarp();
    }
}

// ---------------- z1 stats over edges, CSR order ----------------
__global__ __launch_bounds__(256) void k_zstats(int slot, const float* __restrict__ W1row) {
    __shared__ float ssum[HH], ssq[HH];
    int tid = threadIdx.x;
    if (tid < HH) { ssum[tid] = 0.0f; ssq[tid] = 0.0f; }
    __syncthreads();

    int warp = tid >> 5, lane = tid & 31;
    int n = blockIdx.x * 8 + warp;
    float we0 = W1row[lane], we1 = W1row[lane + 32];
    float ls0 = 0.f, lq0 = 0.f, ls1 = 0.f, lq1 = 0.f;
    if (n < NN) {
        float pt0 = g_pt[n * HH + lane], pt1 = g_pt[n * HH + 32 + lane];
        int beg = g_off[n], cnt = g_degi[n];
        #pragma unroll 4
        for (int i = 0; i < cnt; i++) {
            int2 ce = __ldg(&g_cedge[beg + i]);
            float ev = __int_as_float(ce.y);
            float2 pf = __half22float2(g_pmh[ce.x * 32 + lane]);
            float z0 = pt0 + pf.x + ev * we0;
            float z1 = pt1 + pf.y + ev * we1;
            ls0 += z0; lq0 += z0 * z0;
            ls1 += z1; lq1 += z1 * z1;
        }
    }
    atomicAdd(&ssum[lane], ls0);
    atomicAdd(&ssum[lane + 32], ls1);
    atomicAdd(&ssq[lane], lq0);
    atomicAdd(&ssq[lane + 32], lq1);
    __syncthreads();
    if (tid < HH) {
        atomicAdd(&g_sumA[slot * HH + tid], ssum[tid]);
        atomicAdd(&g_sqA[slot * HH + tid], ssq[tid]);
    }
}

// ---------------- aggy[n] = sum_{e in(n)} silu(BN(z1_e)), CSR, no atomics ----
__global__ __launch_bounds__(256) void k_aggy(int slot, const float* __restrict__ W1row,
                                              const float* __restrict__ gam,
                                              const float* __restrict__ bet) {
    int tid = threadIdx.x;
    int warp = tid >> 5, lane = tid & 31;
    int n = blockIdx.x * 8 + warp;
    if (n >= NN) return;
    float we0 = W1row[lane], we1 = W1row[lane + 32];
    float ga0, ga1, gb0, gb1;
    bn_coef(slot, lane,      gam, bet, (float)EE, ga0, gb0);
    bn_coef(slot, lane + 32, gam, bet, (float)EE, ga1, gb1);
    float pt0 = g_pt[n * HH + lane], pt1 = g_pt[n * HH + 32 + lane];
    int beg = g_off[n], cnt = g_degi[n];
    float acc0 = 0.f, acc1 = 0.f;
    #pragma unroll 4
    for (int i = 0; i < cnt; i++) {
        int2 ce = __ldg(&g_cedge[beg + i]);
        float ev = __int_as_float(ce.y);
        float2 pf = __half22float2(g_pmh[ce.x * 32 + lane]);
        float z0 = pt0 + pf.x + ev * we0;
        float z1 = pt1 + pf.y + ev * we1;
        acc0 += silu_fast(z0 * ga0 + gb0);
        acc1 += silu_fast(z1 * ga1 + gb1);
    }
    g_aggy[n * HH + lane]      = acc0;
    g_aggy[n * HH + lane + 32] = acc1;
}

// ---------------- update: u = h@Wu_top + (aggy/deg)@Wc + b ; stats -> slot ---
__global__ __launch_bounds__(256) void k_upd1f(int l, const float* __restrict__ Wu,
                                               const float* __restrict__ b) {
    __shared__ float4 sW[32 * 64];               // 32KB
    __shared__ alignas(16) float si[8][4][128];  // 16KB (reused for reduction)
    int tid = threadIdx.x;
    const float* wc = g_wcA + (size_t)l * HH * HH;
    for (int idx = tid; idx < 32 * 64; idx += 256) {
        int c = idx & 63, k4 = idx >> 6;
        const float* srcp = (k4 < 16) ? (Wu + (4 * k4) * HH + c)
                                      : (wc + (4 * (k4 - 16)) * HH + c);
        sW[idx] = make_float4(srcp[0], srcp[HH], srcp[2 * HH], srcp[3 * HH]);
    }
    __syncthreads();

    int warp = tid >> 5, lane = tid & 31;
    float b0 = b[lane], b1v = b[lane + 32];
    float bc0 = g_bcA[l * HH + lane], bc1 = g_bcA[l * HH + lane + 32];
    float ls0 = 0.f, lq0 = 0.f, ls1 = 0.f, lq1 = 0.f;
    float (*is_)[128] = si[warp];
    int tile = blockIdx.x * 8 + warp, ts = gridDim.x * 8;
    const int NT = NN / 4;
    for (int t = tile; t < NT; t += ts) {
        int n0 = t * 4;
        float fl[4];
        #pragma unroll
        for (int e = 0; e < 4; e++) {
            int n = n0 + e;
            int dg = g_degi[n];
            float inv = (dg > 0) ? (1.0f / (float)dg) : 0.0f;
            fl[e] = (dg > 0) ? 1.0f : 0.0f;
            is_[e][lane]      = g_h[n * HH + lane];
            is_[e][32 + lane] = g_h[n * HH + 32 + lane];
            is_[e][64 + lane] = g_aggy[n * HH + lane] * inv;
            is_[e][96 + lane] = g_aggy[n * HH + 32 + lane] * inv;
        }
        __syncwarp();
        float a0[4], a1[4];
        #pragma unroll
        for (int e = 0; e < 4; e++) {
            a0[e] = b0 + fl[e] * bc0;
            a1[e] = b1v + fl[e] * bc1;
        }
        #pragma unroll
        for (int k4 = 0; k4 < 32; k4++) {
            float4 w0 = sW[k4 * 64 + lane];
            float4 w1 = sW[k4 * 64 + 32 + lane];
            #pragma unroll
            for (int e = 0; e < 4; e++) {
                float4 xv = *(const float4*)&is_[e][k4 * 4];
                a0[e] += xv.x * w0.x; a0[e] += xv.y * w0.y;
                a0[e] += xv.z * w0.z; a0[e] += xv.w * w0.w;
                a1[e] += xv.x * w1.x; a1[e] += xv.y * w1.y;
                a1[e] += xv.z * w1.z; a1[e] += xv.w * w1.w;
            }
        }
        #pragma unroll
        for (int e = 0; e < 4; e++) {
            int n = n0 + e;
            g_u[n * HH + lane]      = a0[e];
            g_u[n * HH + lane + 32] = a1[e];
            ls0 += a0[e]; lq0 += a0[e] * a0[e];
            ls1 += a1[e]; lq1 += a1[e] * a1[e];
        }
        __syncwarp();
    }
    __syncthreads();
    float* ssum = &si[0][0][0];
    float* ssq  = &si[0][0][64];
    if (tid < HH) { ssum[tid] = 0.0f; ssq[tid] = 0.0f; }
    __syncthreads();
    atomicAdd(&ssum[lane], ls0);
    atomicAdd(&ssum[lane + 32], ls1);
    atomicAdd(&ssq[lane], lq0);
    atomicAdd(&ssq[lane + 32], lq1);
    __syncthreads();
    int slot = 2 * l + 1;
    if (tid < HH) {
        atomicAdd(&g_sumA[slot * HH + tid], ssum[tid]);
        atomicAdd(&g_sqA[slot * HH + tid], ssq[tid]);
    }
}

// ---------------- pool with fused final activation: h=silu(BN(u)) -----------
__global__ void k_pool(const int* __restrict__ batch, const float* __restrict__ gam,
                       const float* __restrict__ bet) {
    int tid = threadIdx.x;
    int warp = tid >> 5, lane = tid & 31;
    int n = blockIdx.x * 8 + warp;
    if (n >= NN) return;
    const int slot = 2 * (LL - 1) + 1;
    float ga0, ga1, gb0, gb1;
    bn_coef(slot, lane,      gam, bet, (float)NN, ga0, gb0);
    bn_coef(slot, lane + 32, gam, bet, (float)NN, ga1, gb1);
    int b = batch[n];
    float h0 = silu_f(g_u[n * HH + lane]      * ga0 + gb0);
    float h1 = silu_f(g_u[n * HH + lane + 32] * ga1 + gb1);
    atomicAdd(&g_pool[b * HH + lane], h0);
    atomicAdd(&g_pool[b * HH + lane + 32], h1);
    if (lane == 0) atomicAdd(&g_cnt[b], 1.0f);
}

// ---------------- output projection ----------------
__global__ void k_out(const float* __restrict__ W, const float* __restrict__ b,
                      float* __restrict__ out) {
    __shared__ float sg[HH];
    int gi = blockIdx.x;
    int c = threadIdx.x;
    sg[c] = g_pool[gi * HH + c] / fmaxf(g_cnt[gi], 1.0f);
    __syncthreads();
    float acc = b[c];
    #pragma unroll
    for (int k = 0; k < HH; k++) acc += sg[k] * W[k * HH + c];
    out[gi * HH + c] = silu_f(acc);
}

// ---------------- launch ----------------
extern "C" void kernel_launch(void* const* d_in, const int* in_sizes, int n_in,
                              void* d_out, int out_size) {
    const float* x         = (const float*)d_in[0];
    const float* edge_attr = (const float*)d_in[1];
    const int*   edge_idx  = (const int*)  d_in[2];
    const int*   batch     = (const int*)  d_in[3];
    const float* node_W    = (const float*)d_in[4];
    const float* node_b    = (const float*)d_in[5];
    const float* msg_W1    = (const float*)d_in[6];
    const float* msg_b1    = (const float*)d_in[7];
    const float* msg_g1    = (const float*)d_in[8];
    const float* msg_be1   = (const float*)d_in[9];
    const float* msg_W2    = (const float*)d_in[10];
    const float* msg_b2    = (const float*)d_in[11];
    const float* upd_W     = (const float*)d_in[12];
    const float* upd_b     = (const float*)d_in[13];
    const float* upd_g     = (const float*)d_in[14];
    const float* upd_be    = (const float*)d_in[15];
    const float* out_W     = (const float*)d_in[16];
    const float* out_b     = (const float*)d_in[17];
    float* out = (float*)d_out;

    const int* src = edge_idx;
    const int* dst = edge_idx + EE;

    const int NB = (NN + 7) / 8;   // warp-per-node grids

    k_init<<<256, 256>>>();
    k_foldw<<<dim3(17, LL), 256>>>(msg_W2, upd_W, msg_b2);   // input-only, hoisted
    k_embed<<<592, 256>>>(x, node_W, node_b);
    k_deg<<<1024, 256>>>(dst);
    k_scan1<<<NSCAN, 256>>>();
    k_scan3<<<NSCAN, 256>>>();
    k_scatter<<<1024, 256>>>(src, dst, edge_attr);

    for (int l = 0; l < LL; l++) {
        const float* W1l   = msg_W1 + (size_t)l * M1 * HH;
        const float* W1row = W1l + 128 * HH;
        // k_pre fuses previous layer's h = silu(BN(u)) via its stat slot
        k_pre<<<296, 256>>>(W1l, msg_b1 + l * HH,
                            upd_g + (l > 0 ? (l - 1) : 0) * HH,
                            upd_be + (l > 0 ? (l - 1) : 0) * HH,
                            l > 0 ? 2 * (l - 1) + 1 : -1);
        k_zstats<<<NB, 256>>>(2 * l, W1row);
        k_aggy<<<NB, 256>>>(2 * l, W1row, msg_g1 + l * HH, msg_be1 + l * HH);
        k_upd1f<<<296, 256>>>(l, upd_W + (size_t)l * 2 * HH * HH, upd_b + l * HH);
    }

    k_pool<<<NB, 256>>>(batch, upd_g + (LL - 1) * HH, upd_be + (LL - 1) * HH);
    k_out<<<GG, 64>>>(out_W, out_b, out);
}

// round 12
// speedup vs baseline: 1.4988x; 1.4988x over previous
#include <cuda_runtime.h>
#include <cuda_fp16.h>

#define NN  50000
#define EE  1200000
#define NIDD 92
#define HH  64
#define LL  5
#define GG  256
#define M1  129   // 2H + ED
#define NSCAN 196 // ceil(NN/256)

// ---------------- device scratch (no mallocs allowed) ----------------
__device__ float   g_h[NN * HH];        // node features (post-activation)
__device__ float   g_u[NN * HH];        // update pre-activation
__device__ float   g_aggy[NN * HH];     // sum of silu(BN(z1)) over incoming edges
__device__ float   g_pt[NN * HH];       // h @ W1[0:64] + b1 (dst part), fp32
__device__ __half2 g_pmh[NN * 32];      // h @ W1[64:128] (src part), packed (c, c+32)
__device__ int     g_degi[NN];          // in-degree
__device__ int     g_off[NN];           // CSR offsets
__device__ int     g_cur[NN];           // CSR scatter cursors
__device__ int     g_bsum[NSCAN];       // scan block sums (raw)
__device__ int2    g_cedge[EE];         // CSR: (src, ea bits) per slot
__device__ float   g_sumA[2 * LL * HH]; // BN stat slots (2 per layer)
__device__ float   g_sqA[2 * LL * HH];
__device__ float   g_wcA[LL * HH * HH]; // W2 @ updW_bot per layer
__device__ float   g_bcA[LL * HH];      // b2 @ updW_bot per layer
__device__ float   g_pool[GG * HH];
__device__ float   g_cnt[GG];

__device__ __forceinline__ float silu_f(float x) {
    return __fdividef(x, 1.0f + __expf(-x));
}

// fast silu: 1 MUFU (tanh.approx) instead of 2 (ex2 + rcp)
// silu(x) = x*sigmoid(x) = 0.5x*(1 + tanh(0.5x))
__device__ __forceinline__ float silu_fast(float x) {
    float h = 0.5f * x;
    float t;
    asm("tanh.approx.f32 %0, %1;" : "=f"(t) : "f"(h));
    return fmaf(h, t, h);
}

// inline BN coefficient finalize from a stat slot
__device__ __forceinline__ void bn_coef(int slot, int c, const float* __restrict__ gam,
                                        const float* __restrict__ bet, float denom,
                                        float& a, float& b) {
    float mean = g_sumA[slot * HH + c] / denom;
    float var  = g_sqA[slot * HH + c] / denom - mean * mean;
    float inv  = rsqrtf(var + 1e-5f);
    a = gam[c] * inv;
    b = bet[c] - mean * a;
}

// ---------------- init ----------------
__global__ void k_init() {
    int i = blockIdx.x * blockDim.x + threadIdx.x;
    int stride = gridDim.x * blockDim.x;
    for (int t = i; t < NN; t += stride) g_degi[t] = 0;
    for (int t = i; t < GG * HH; t += stride) g_pool[t] = 0.0f;
    for (int t = i; t < GG; t += stride) g_cnt[t] = 0.0f;
    for (int t = i; t < 2 * LL * HH; t += stride) { g_sumA[t] = 0.0f; g_sqA[t] = 0.0f; }
}

// ---------------- fold (all layers, hoisted): Wc = W2@Wu_bot ; bc = b2@Wu_bot -
__global__ void k_foldw(const float* __restrict__ W2all, const float* __restrict__ Wuall,
                        const float* __restrict__ b2all) {
    int l = blockIdx.y;
    const float* W2 = W2all + (size_t)l * HH * HH;
    const float* Wu = Wuall + (size_t)l * 2 * HH * HH;
    const float* b2 = b2all + l * HH;
    int i = blockIdx.x * blockDim.x + threadIdx.x;
    if (i < HH * HH) {
        int k = i >> 6, c = i & 63;
        float acc = 0.f;
        #pragma unroll 8
        for (int j = 0; j < HH; j++)
            acc += __ldg(&W2[k * HH + j]) * __ldg(&Wu[(HH + j) * HH + c]);
        g_wcA[l * HH * HH + i] = acc;
    } else if (i < HH * HH + HH) {
        int c = i - HH * HH;
        float acc = 0.f;
        #pragma unroll 8
        for (int j = 0; j < HH; j++)
            acc += __ldg(&b2[j]) * __ldg(&Wu[(HH + j) * HH + c]);
        g_bcA[l * HH + c] = acc;
    }
}

// ---------------- node embedding: h = x @ node_W + node_b ----------------
__global__ __launch_bounds__(256) void k_embed(const float* __restrict__ x,
                                               const float* __restrict__ W,
                                               const float* __restrict__ b) {
    __shared__ float sW[NIDD * HH];     // 23.5KB
    __shared__ float sx[8][NIDD];
    int tid = threadIdx.x;
    for (int i = tid; i < NIDD * HH; i += 256) sW[i] = W[i];
    __syncthreads();

    int warp = tid >> 5, lane = tid & 31;
    int gw = blockIdx.x * 8 + warp;
    int ws = gridDim.x * 8;
    float* xs = sx[warp];
    float b0 = b[lane], b1v = b[lane + 32];
    for (int n = gw; n < NN; n += ws) {
        xs[lane] = x[n * NIDD + lane];
        xs[32 + lane] = x[n * NIDD + 32 + lane];
        if (lane < NIDD - 64) xs[64 + lane] = x[n * NIDD + 64 + lane];
        __syncwarp();
        float a0 = b0, a1 = b1v;
        const float* wp = sW + lane;
        #pragma unroll 4
        for (int k = 0; k < NIDD; k++) {
            float xv = xs[k];
            a0 += xv * wp[0];
            a1 += xv * wp[32];
            wp += HH;
        }
        g_h[n * HH + lane] = a0;
        g_h[n * HH + lane + 32] = a1;
        __syncwarp();
    }
}

// ---------------- degree histogram ----------------
__global__ void k_deg(const int* __restrict__ dst) {
    int i = blockIdx.x * blockDim.x + threadIdx.x;
    int stride = gridDim.x * blockDim.x;
    for (int e = i; e < EE; e += stride) atomicAdd(&g_degi[dst[e]], 1);
}

// ---------------- scan phase 1: coalesced per-block sums ----------------
__global__ __launch_bounds__(256) void k_scan1() {
    int idx = blockIdx.x * 256 + threadIdx.x;
    int v = (idx < NN) ? g_degi[idx] : 0;
    #pragma unroll
    for (int o = 16; o; o >>= 1) v += __shfl_down_sync(0xffffffffu, v, o);
    __shared__ int ws[8];
    if ((threadIdx.x & 31) == 0) ws[threadIdx.x >> 5] = v;
    __syncthreads();
    if (threadIdx.x < 8) {
        int t = ws[threadIdx.x];
        #pragma unroll
        for (int o = 4; o; o >>= 1) t += __shfl_down_sync(0xffu, t, o);
        if (threadIdx.x == 0) g_bsum[blockIdx.x] = t;
    }
}

// ---------------- scan phase 2+3 merged: every block redundantly scans the
// 196 block sums in smem, then does its local exclusive scan + offset --------
__global__ __launch_bounds__(256) void k_scan3() {
    __shared__ int sb[256];
    __shared__ int s[256];
    int t = threadIdx.x;
    int bv = (t < NSCAN) ? g_bsum[t] : 0;
    sb[t] = bv;
    __syncthreads();
    #pragma unroll
    for (int o = 1; o < 256; o <<= 1) {
        int u = (t >= o) ? sb[t - o] : 0;
        __syncthreads();
        sb[t] += u;
        __syncthreads();
    }
    int blockOff = (blockIdx.x == 0) ? 0 : sb[blockIdx.x - 1];

    int idx = blockIdx.x * 256 + t;
    int v = (idx < NN) ? g_degi[idx] : 0;
    s[t] = v;
    __syncthreads();
    #pragma unroll
    for (int o = 1; o < 256; o <<= 1) {
        int u = (t >= o) ? s[t - o] : 0;
        __syncthreads();
        s[t] += u;
        __syncthreads();
    }
    int excl = s[t] - v + blockOff;
    if (idx < NN) { g_off[idx] = excl; g_cur[idx] = excl; }
}

// ---------------- CSR scatter: place (src, ea) by dst ----------------
__global__ void k_scatter(const int* __restrict__ src, const int* __restrict__ dst,
                          const float* __restrict__ ea) {
    int i = blockIdx.x * blockDim.x + threadIdx.x;
    int stride = gridDim.x * blockDim.x;
    for (int e = i; e < EE; e += stride) {
        int d = dst[e];
        int p = atomicAdd(&g_cur[d], 1);
        g_cedge[p] = make_int2(src[e], __float_as_int(ea[e]));
    }
}

// ---------------- per-node precompute: pt = h@W1_top + b1 ; pmh = h@W1_mid ---
// If prev_slot >= 0: h is first recomputed as silu(BN(u)) using that stat slot
// (fused update pass2 of the previous layer) and written back to g_h.
__global__ __launch_bounds__(256) void k_pre(const float* __restrict__ W1,
                                             const float* __restrict__ b1,
                                             const float* __restrict__ gamP,
                                             const float* __restrict__ betP,
                                             int prev_slot) {
    __shared__ float4 sW[16 * 128];              // 32KB
    __shared__ alignas(16) float sh[8][4][64];   // 8KB
    int tid = threadIdx.x;
    for (int idx = tid; idx < 16 * 128; idx += 256) {
        int c2 = idx & 127, k4 = idx >> 7;
        int col = c2 & 63;
        int row = (c2 < 64 ? 4 * k4 : 64 + 4 * k4);
        sW[idx] = make_float4(W1[row * HH + col], W1[(row + 1) * HH + col],
                              W1[(row + 2) * HH + col], W1[(row + 3) * HH + col]);
    }
    __syncthreads();

    int warp = tid >> 5, lane = tid & 31;
    float bt0 = b1[lane], bt1 = b1[lane + 32];
    float ga0 = 0.f, ga1 = 0.f, gb0 = 0.f, gb1 = 0.f;
    if (prev_slot >= 0) {
        bn_coef(prev_slot, lane,      gamP, betP, (float)NN, ga0, gb0);
        bn_coef(prev_slot, lane + 32, gamP, betP, (float)NN, ga1, gb1);
    }
    float (*hs)[64] = sh[warp];
    int tile = blockIdx.x * 8 + warp, ts = gridDim.x * 8;
    const int NT = NN / 4;
    for (int t = tile; t < NT; t += ts) {
        int n0 = t * 4;
        #pragma unroll
        for (int e = 0; e < 4; e++) {
            int n = n0 + e;
            float h0, h1;
            if (prev_slot >= 0) {
                h0 = silu_f(g_u[n * HH + lane]      * ga0 + gb0);
                h1 = silu_f(g_u[n * HH + lane + 32] * ga1 + gb1);
                g_h[n * HH + lane]      = h0;
                g_h[n * HH + lane + 32] = h1;
            } else {
                h0 = g_h[n * HH + lane];
                h1 = g_h[n * HH + lane + 32];
            }
            hs[e][lane]      = h0;
            hs[e][lane + 32] = h1;
        }
        __syncwarp();
        float a0[4], a1[4], a2[4], a3[4];
        #pragma unroll
        for (int e = 0; e < 4; e++) { a0[e] = 0.f; a1[e] = 0.f; a2[e] = 0.f; a3[e] = 0.f; }
        #pragma unroll
        for (int k4 = 0; k4 < 16; k4++) {
            float4 wA = sW[k4 * 128 + lane];
            float4 wB = sW[k4 * 128 + 32 + lane];
            float4 wC = sW[k4 * 128 + 64 + lane];
            float4 wD = sW[k4 * 128 + 96 + lane];
            #pragma unroll
            for (int e = 0; e < 4; e++) {
                float4 hv = *(const float4*)&hs[e][k4 * 4];
                a0[e] += hv.x * wA.x; a0[e] += hv.y * wA.y; a0[e] += hv.z * wA.z; a0[e] += hv.w * wA.w;
                a1[e] += hv.x * wB.x; a1[e] += hv.y * wB.y; a1[e] += hv.z * wB.z; a1[e] += hv.w * wB.w;
                a2[e] += hv.x * wC.x; a2[e] += hv.y * wC.y; a2[e] += hv.z * wC.z; a2[e] += hv.w * wC.w;
                a3[e] += hv.x * wD.x; a3[e] += hv.y * wD.y; a3[e] += hv.z * wD.z; a3[e] += hv.w * wD.w;
            }
        }
        #pragma unroll
        for (int e = 0; e < 4; e++) {
            int n = n0 + e;
            g_pt[n * HH + lane]      = a0[e] + bt0;
            g_pt[n * HH + lane + 32] = a1[e] + bt1;
            g_pmh[n * 32 + lane]     = __floats2half2_rn(a2[e], a3[e]);
        }
        __syncwarp();
    }
}

// ---------------- z1 stats over edges, CSR order ----------------
__global__ __launch_bounds__(256) void k_zstats(int slot, const float* __restrict__ W1row) {
    __shared__ float ssum[HH], ssq[HH];
    int tid = threadIdx.x;
    if (tid < HH) { ssum[tid] = 0.0f; ssq[tid] = 0.0f; }
    __syncthreads();

    int warp = tid >> 5, lane = tid & 31;
    int n = blockIdx.x * 8 + warp;
    float we0 = W1row[lane], we1 = W1row[lane + 32];
    float ls0 = 0.f, lq0 = 0.f, ls1 = 0.f, lq1 = 0.f;
    if (n < NN) {
        float pt0 = g_pt[n * HH + lane], pt1 = g_pt[n * HH + 32 + lane];
        int beg = g_off[n], cnt = g_degi[n];
        #pragma unroll 4
        for (int i = 0; i < cnt; i++) {
            int2 ce = __ldg(&g_cedge[beg + i]);
            float ev = __int_as_float(ce.y);
            float2 pf = __half22float2(g_pmh[ce.x * 32 + lane]);
            float z0 = pt0 + pf.x + ev * we0;
            float z1 = pt1 + pf.y + ev * we1;
            ls0 += z0; lq0 += z0 * z0;
            ls1 += z1; lq1 += z1 * z1;
        }
    }
    atomicAdd(&ssum[lane], ls0);
    atomicAdd(&ssum[lane + 32], ls1);
    atomicAdd(&ssq[lane], lq0);
    atomicAdd(&ssq[lane + 32], lq1);
    __syncthreads();
    if (tid < HH) {
        atomicAdd(&g_sumA[slot * HH + tid], ssum[tid]);
        atomicAdd(&g_sqA[slot * HH + tid], ssq[tid]);
    }
}

// ---------------- aggy[n] = sum_{e in(n)} silu(BN(z1_e)), CSR, no atomics ----
__global__ __launch_bounds__(256) void k_aggy(int slot, const float* __restrict__ W1row,
                                              const float* __restrict__ gam,
                                              const float* __restrict__ bet) {
    int tid = threadIdx.x;
    int warp = tid >> 5, lane = tid & 31;
    int n = blockIdx.x * 8 + warp;
    if (n >= NN) return;
    float we0 = W1row[lane], we1 = W1row[lane + 32];
    float ga0, ga1, gb0, gb1;
    bn_coef(slot, lane,      gam, bet, (float)EE, ga0, gb0);
    bn_coef(slot, lane + 32, gam, bet, (float)EE, ga1, gb1);
    float pt0 = g_pt[n * HH + lane], pt1 = g_pt[n * HH + 32 + lane];
    int beg = g_off[n], cnt = g_degi[n];
    float acc0 = 0.f, acc1 = 0.f;
    #pragma unroll 4
    for (int i = 0; i < cnt; i++) {
        int2 ce = __ldg(&g_cedge[beg + i]);
        float ev = __int_as_float(ce.y);
        float2 pf = __half22float2(g_pmh[ce.x * 32 + lane]);
        float z0 = pt0 + pf.x + ev * we0;
        float z1 = pt1 + pf.y + ev * we1;
        acc0 += silu_fast(z0 * ga0 + gb0);
        acc1 += silu_fast(z1 * ga1 + gb1);
    }
    g_aggy[n * HH + lane]      = acc0;
    g_aggy[n * HH + lane + 32] = acc1;
}

// ---------------- update: u = h@Wu_top + (aggy/deg)@Wc + b ; stats -> slot ---
__global__ __launch_bounds__(256) void k_upd1f(int l, const float* __restrict__ Wu,
                                               const float* __restrict__ b) {
    __shared__ float4 sW[32 * 64];               // 32KB
    __shared__ alignas(16) float si[8][4][128];  // 16KB (reused for reduction)
    int tid = threadIdx.x;
    const float* wc = g_wcA + (size_t)l * HH * HH;
    for (int idx = tid; idx < 32 * 64; idx += 256) {
        int c = idx & 63, k4 = idx >> 6;
        const float* srcp = (k4 < 16) ? (Wu + (4 * k4) * HH + c)
                                      : (wc + (4 * (k4 - 16)) * HH + c);
        sW[idx] = make_float4(srcp[0], srcp[HH], srcp[2 * HH], srcp[3 * HH]);
    }
    __syncthreads();

    int warp = tid >> 5, lane = tid & 31;
    float b0 = b[lane], b1v = b[lane + 32];
    float bc0 = g_bcA[l * HH + lane], bc1 = g_bcA[l * HH + lane + 32];
    float ls0 = 0.f, lq0 = 0.f, ls1 = 0.f, lq1 = 0.f;
    float (*is_)[128] = si[warp];
    int tile = blockIdx.x * 8 + warp, ts = gridDim.x * 8;
    const int NT = NN / 4;
    for (int t = tile; t < NT; t += ts) {
        int n0 = t * 4;
        float fl[4];
        #pragma unroll
        for (int e = 0; e < 4; e++) {
            int n = n0 + e;
            int dg = g_degi[n];
            float inv = (dg > 0) ? (1.0f / (float)dg) : 0.0f;
            fl[e] = (dg > 0) ? 1.0f : 0.0f;
            is_[e][lane]      = g_h[n * HH + lane];
            is_[e][32 + lane] = g_h[n * HH + 32 + lane];
            is_[e][64 + lane] = g_aggy[n * HH + lane] * inv;
            is_[e][96 + lane] = g_aggy[n * HH + 32 + lane] * inv;
        }
        __syncwarp();
        float a0[4], a1[4];
        #pragma unroll
        for (int e = 0; e < 4; e++) {
            a0[e] = b0 + fl[e] * bc0;
            a1[e] = b1v + fl[e] * bc1;
        }
        #pragma unroll
        for (int k4 = 0; k4 < 32; k4++) {
            float4 w0 = sW[k4 * 64 + lane];
            float4 w1 = sW[k4 * 64 + 32 + lane];
            #pragma unroll
            for (int e = 0; e < 4; e++) {
                float4 xv = *(const float4*)&is_[e][k4 * 4];
                a0[e] += xv.x * w0.x; a0[e] += xv.y * w0.y;
                a0[e] += xv.z * w0.z; a0[e] += xv.w * w0.w;
                a1[e] += xv.x * w1.x; a1[e] += xv.y * w1.y;
                a1[e] += xv.z * w1.z; a1[e] += xv.w * w1.w;
            }
        }
        #pragma unroll
        for (int e = 0; e < 4; e++) {
            int n = n0 + e;
            g_u[n * HH + lane]      = a0[e];
            g_u[n * HH + lane + 32] = a1[e];
            ls0 += a0[e]; lq0 += a0[e] * a0[e];
            ls1 += a1[e]; lq1 += a1[e] * a1[e];
        }
        __syncwarp();
    }
    __syncthreads();
    float* ssum = &si[0][0][0];
    float* ssq  = &si[0][0][64];
    if (tid < HH) { ssum[tid] = 0.0f; ssq[tid] = 0.0f; }
    __syncthreads();
    atomicAdd(&ssum[lane], ls0);
    atomicAdd(&ssum[lane + 32], ls1);
    atomicAdd(&ssq[lane], lq0);
    atomicAdd(&ssq[lane + 32], lq1);
    __syncthreads();
    int slot = 2 * l + 1;
    if (tid < HH) {
        atomicAdd(&g_sumA[slot * HH + tid], ssum[tid]);
        atomicAdd(&g_sqA[slot * HH + tid], ssq[tid]);
    }
}

// ---------------- pool with fused final activation: h=silu(BN(u)) -----------
__global__ void k_pool(const int* __restrict__ batch, const float* __restrict__ gam,
                       const float* __restrict__ bet) {
    int tid = threadIdx.x;
    int warp = tid >> 5, lane = tid & 31;
    int n = blockIdx.x * 8 + warp;
    if (n >= NN) return;
    const int slot = 2 * (LL - 1) + 1;
    float ga0, ga1, gb0, gb1;
    bn_coef(slot, lane,      gam, bet, (float)NN, ga0, gb0);
    bn_coef(slot, lane + 32, gam, bet, (float)NN, ga1, gb1);
    int b = batch[n];
    float h0 = silu_f(g_u[n * HH + lane]      * ga0 + gb0);
    float h1 = silu_f(g_u[n * HH + lane + 32] * ga1 + gb1);
    atomicAdd(&g_pool[b * HH + lane], h0);
    atomicAdd(&g_pool[b * HH + lane + 32], h1);
    if (lane == 0) atomicAdd(&g_cnt[b], 1.0f);
}

// ---------------- output projection ----------------
__global__ void k_out(const float* __restrict__ W, const float* __restrict__ b,
                      float* __restrict__ out) {
    __shared__ float sg[HH];
    int gi = blockIdx.x;
    int c = threadIdx.x;
    sg[c] = g_pool[gi * HH + c] / fmaxf(g_cnt[gi], 1.0f);
    __syncthreads();
    float acc = b[c];
    #pragma unroll
    for (int k = 0; k < HH; k++) acc += sg[k] * W[k * HH + c];
    out[gi * HH + c] = silu_f(acc);
}

// ---------------- launch ----------------
extern "C" void kernel_launch(void* const* d_in, const int* in_sizes, int n_in,
                              void* d_out, int out_size) {
    const float* x         = (const float*)d_in[0];
    const float* edge_attr = (const float*)d_in[1];
    const int*   edge_idx  = (const int*)  d_in[2];
    const int*   batch     = (const int*)  d_in[3];
    const float* node_W    = (const float*)d_in[4];
    const float* node_b    = (const float*)d_in[5];
    const float* msg_W1    = (const float*)d_in[6];
    const float* msg_b1    = (const float*)d_in[7];
    const float* msg_g1    = (const float*)d_in[8];
    const float* msg_be1   = (const float*)d_in[9];
    const float* msg_W2    = (const float*)d_in[10];
    const float* msg_b2    = (const float*)d_in[11];
    const float* upd_W     = (const float*)d_in[12];
    const float* upd_b     = (const float*)d_in[13];
    const float* upd_g     = (const float*)d_in[14];
    const float* upd_be    = (const float*)d_in[15];
    const float* out_W     = (const float*)d_in[16];
    const float* out_b     = (const float*)d_in[17];
    float* out = (float*)d_out;

    const int* src = edge_idx;
    const int* dst = edge_idx + EE;

    const int NB = (NN + 7) / 8;   // warp-per-node grids

    k_init<<<256, 256>>>();
    k_foldw<<<dim3(17, LL), 256>>>(msg_W2, upd_W, msg_b2);   // input-only, hoisted
    k_embed<<<592, 256>>>(x, node_W, node_b);
    k_deg<<<1024, 256>>>(dst);
    k_scan1<<<NSCAN, 256>>>();
    k_scan3<<<NSCAN, 256>>>();
    k_scatter<<<1024, 256>>>(src, dst, edge_attr);

    for (int l = 0; l < LL; l++) {
        const float* W1l   = msg_W1 + (size_t)l * M1 * HH;
        const float* W1row = W1l + 128 * HH;
        // k_pre fuses previous layer's h = silu(BN(u)) via its stat slot
        k_pre<<<296, 256>>>(W1l, msg_b1 + l * HH,
                            upd_g + (l > 0 ? (l - 1) : 0) * HH,
                            upd_be + (l > 0 ? (l - 1) : 0) * HH,
                            l > 0 ? 2 * (l - 1) + 1 : -1);
        k_zstats<<<NB, 256>>>(2 * l, W1row);
        k_aggy<<<NB, 256>>>(2 * l, W1row, msg_g1 + l * HH, msg_be1 + l * HH);
        k_upd1f<<<296, 256>>>(l, upd_W + (size_t)l * 2 * HH * HH, upd_b + l * HH);
    }

    k_pool<<<NB, 256>>>(batch, upd_g + (LL - 1) * HH, upd_be + (LL - 1) * HH);
    k_out<<<GG, 64>>>(out_W, out_b, out);
}